// round 8
// baseline (speedup 1.0000x reference)
#include <cuda_runtime.h>
#include <cuda_fp16.h>

// ---------------- problem constants ----------------
#define Bn 65536
#define Cn 128
#define Dn 32
#define Kn 10
#define NAUG 33
#define KPAD 576          // padded triangular size (9 chunks of 64)
#define KC 64
#define NCH 9
#define ROWS 128
#define NBLK 512          // Bn / ROWS
#define THREADS 512
#define TILE 16384        // 128 x 64 fp16, 128B rows, SW128

#define SWZ(o) ((o) ^ (((o) >> 3) & 0x70))

// pre-split fp16 U tiles, pre-swizzled: [split][chunk][16KB]
__device__ __align__(16) unsigned char g_Uh[2][NCH][TILE];
// materialized A tiles: per rowblock, per chunk: [split0 16KB | split1 16KB]
__device__ __align__(16) unsigned char g_A[(size_t)NBLK * NCH * 2 * TILE];
__device__ int g_ij[KPAD];     // (i | j<<8)
__device__ int g_cls[Cn];

// ---------------- helpers ----------------
static __device__ __forceinline__ unsigned smem_u32(const void* p) {
    unsigned a;
    asm("{ .reg .u64 t; cvta.to.shared.u64 t, %1; cvt.u32.u64 %0, t; }"
        : "=r"(a) : "l"(p));
    return a;
}
static __device__ __forceinline__ void cp16(unsigned sdst, const void* gsrc) {
    asm volatile("cp.async.cg.shared.global [%0], [%1], 16;" :: "r"(sdst), "l"(gsrc));
}
static __device__ __forceinline__ void ldsm4(unsigned base, int row0, int kb,
                                             int lane, unsigned* r) {
    unsigned off = (unsigned)((row0 + (lane & 15)) * 128 + kb + ((lane >> 4) << 4));
    unsigned addr = base + SWZ(off);
    asm volatile("ldmatrix.sync.aligned.m8n8.x4.shared.b16 {%0,%1,%2,%3}, [%4];"
                 : "=r"(r[0]), "=r"(r[1]), "=r"(r[2]), "=r"(r[3]) : "r"(addr));
}
#define MMA16816(C, A, b0, b1) \
    asm volatile("mma.sync.aligned.m16n8k16.row.col.f32.f16.f16.f32 " \
        "{%0,%1,%2,%3}, {%4,%5,%6,%7}, {%8,%9}, {%0,%1,%2,%3};" \
        : "+f"((C)[0]), "+f"((C)[1]), "+f"((C)[2]), "+f"((C)[3]) \
        : "r"((A)[0]), "r"((A)[1]), "r"((A)[2]), "r"((A)[3]), "r"(b0), "r"(b1))

// ---------------- prep: split U into 2 fp16 tiles (pre-swizzled) ----------------
__global__ void prep_kernel(const float* __restrict__ mu,
                            const float* __restrict__ S,
                            const int* __restrict__ lab) {
    const int c = blockIdx.x;
    const int t = threadIdx.x;   // 32
    __shared__ float mus[Dn], Sm[Dn];

    mus[t] = mu[c * Dn + t];
    __syncwarp();
    float s = 0.f;
#pragma unroll
    for (int e = 0; e < Dn; e++) s += S[(c * Dn + t) * Dn + e] * mus[e];
    Sm[t] = s;
    __syncwarp();
    float t3 = mus[t] * Sm[t];
#pragma unroll
    for (int m = 16; m >= 1; m >>= 1) t3 += __shfl_xor_sync(0xffffffffu, t3, m);

    if (t == 0) {
        int cl = 0;
        for (int k = 0; k < Kn; k++) if (lab[c * Kn + k] != 0) cl = k;
        g_cls[c] = cl;
    }

    for (int k = t; k < KPAD; k += 32) {
        int i = 0, rem = k;
        while (i < NAUG && rem >= NAUG - i) { rem -= NAUG - i; i++; }
        float v; int ii, jj;
        if (i >= NAUG) { v = 0.f; ii = 32; jj = 32; }
        else {
            int j = i + rem; ii = i; jj = j;
            if (j < Dn)      v = ((i == j) ? 1.f : 2.f) * S[(c * Dn + i) * Dn + j];
            else if (i < Dn) v = -2.f * Sm[i];
            else             v = t3;
        }
        if (c == 0) g_ij[k] = ii | (jj << 8);

        __half h0 = __float2half_rn(v);
        float r = v - __half2float(h0);
        __half h1 = __float2half_rn(r);

        int ch = k >> 6, kk = k & 63;
        int sw = SWZ(c * 128 + kk * 2);
        *(__half*)&g_Uh[0][ch][sw] = h0;
        *(__half*)&g_Uh[1][ch][sw] = h1;
    }
}

// ---------------- build: materialize A tiles (fp16 split, swizzled) ----------------
__global__ void __launch_bounds__(256, 4)
build_kernel(const float* __restrict__ data) {
    __shared__ float z_s[ROWS * 36];
    __shared__ int ij_s[KPAD];
    const int tid = threadIdx.x;
    const int bbase = blockIdx.x * ROWS;

    for (int idx = tid; idx < ROWS * Dn; idx += 256) {
        int row = idx >> 5, d = idx & 31;
        z_s[row * 36 + d] = data[(size_t)(bbase + row) * Dn + d];
    }
    if (tid < ROWS) z_s[tid * 36 + 32] = 1.f;
    for (int i = tid; i < KPAD; i += 256) ij_s[i] = g_ij[i];
    __syncthreads();

    for (int ch = 0; ch < NCH; ch++) {
        const size_t off = ((size_t)blockIdx.x * NCH + ch) * (2 * TILE);
#pragma unroll
        for (int pass = 0; pass < 4; pass++) {
            int cell = pass * 256 + tid;   // 1024 cells: row(128) x grp(8)
            int grp = cell & 7, row = cell >> 3;
            const float* zr = z_s + row * 36;
            unsigned p0[4], p1[4];
#pragma unroll
            for (int q = 0; q < 4; q++) {
                int kidx = ch * KC + (grp * 4 + q) * 2;
                int ij0 = ij_s[kidx], ij1 = ij_s[kidx + 1];
                float w0 = zr[ij0 & 255] * zr[ij0 >> 8];
                float w1 = zr[ij1 & 255] * zr[ij1 >> 8];
                __half h00 = __float2half_rn(w0), h01 = __float2half_rn(w1);
                float r0 = w0 - __half2float(h00);
                float r1 = w1 - __half2float(h01);
                __half2 a = __halves2half2(h00, h01);
                __half2 b = __halves2half2(__float2half_rn(r0), __float2half_rn(r1));
                p0[q] = *(unsigned*)&a;
                p1[q] = *(unsigned*)&b;
            }
            unsigned sw = SWZ((unsigned)(row * 128 + grp * 16));
            *(uint4*)(g_A + off + sw)        = make_uint4(p0[0], p0[1], p0[2], p0[3]);
            *(uint4*)(g_A + off + TILE + sw) = make_uint4(p1[0], p1[1], p1[2], p1[3]);
        }
    }
}

// ---------------- gemm kernel smem layout ----------------
#define OFF_CLS 0
#define OFF_LAB 512          // 10*128*4 = 5120
#define OFF_T   6144         // 3 stages x 64KB
#define STAGE   65536
#define SMEM_SZ (OFF_T + 3 * STAGE)   // 202752

__global__ void __launch_bounds__(THREADS, 1)
gemm_kernel(float* __restrict__ out) {
    extern __shared__ char sm_[];
    int*   cls_s = (int*)(sm_ + OFF_CLS);
    float* lab_s = (float*)(sm_ + OFF_LAB);

    const int tid = threadIdx.x;
    const int wid = tid >> 5;
    const int lane = tid & 31;
    const int mw = wid >> 2;          // rows mw*32
    const int nw = wid & 3;           // cols nw*32
    const unsigned sbase = smem_u32(sm_);
    const unsigned tS = sbase + OFF_T;

    if (tid < Cn) cls_s[tid] = g_cls[tid];
    for (int i = tid; i < Kn * ROWS; i += THREADS) lab_s[i] = 0.f;

    const size_t Abase = (size_t)blockIdx.x * NCH * (2 * TILE);

    // prefetch stages 0, 1
#pragma unroll
    for (int st = 0; st < 2; st++) {
        unsigned dst = tS + st * STAGE;
        const unsigned char* srcA = g_A + Abase + (size_t)st * (2 * TILE);
        for (int e = tid; e < 2048; e += THREADS) cp16(dst + e * 16, srcA + e * 16);
        for (int e = tid; e < 1024; e += THREADS)
            cp16(dst + 2 * TILE + e * 16, &g_Uh[0][st][e * 16]);
        for (int e = tid; e < 1024; e += THREADS)
            cp16(dst + 3 * TILE + e * 16, &g_Uh[1][st][e * 16]);
        asm volatile("cp.async.commit_group;");
    }

    float acc[8][4];
#pragma unroll
    for (int i = 0; i < 8; i++)
#pragma unroll
        for (int q = 0; q < 4; q++) acc[i][q] = 0.f;

    for (int ch = 0; ch < NCH; ch++) {
        asm volatile("cp.async.wait_group 1;");
        __syncthreads();   // stage ch visible to all; stage (ch+2)%3 free

        if (ch + 2 < NCH) {
            const int st = ch + 2;
            unsigned dst = tS + (st % 3) * STAGE;
            const unsigned char* srcA = g_A + Abase + (size_t)st * (2 * TILE);
            for (int e = tid; e < 2048; e += THREADS) cp16(dst + e * 16, srcA + e * 16);
            for (int e = tid; e < 1024; e += THREADS)
                cp16(dst + 2 * TILE + e * 16, &g_Uh[0][st][e * 16]);
            for (int e = tid; e < 1024; e += THREADS)
                cp16(dst + 3 * TILE + e * 16, &g_Uh[1][st][e * 16]);
        }
        asm volatile("cp.async.commit_group;");   // always: keep group count uniform

        const unsigned stg = tS + (ch % 3) * STAGE;
        const unsigned A0 = stg, A1 = stg + TILE;
        const unsigned B0 = stg + 2 * TILE, B1 = stg + 3 * TILE;

#pragma unroll
        for (int ks = 0; ks < 4; ks++) {
            const int kb = ks * 32;
            unsigned a0[2][4], a1[2][4];
#pragma unroll
            for (int mf = 0; mf < 2; mf++) {
                ldsm4(A0, mw * 32 + mf * 16, kb, lane, a0[mf]);
                ldsm4(A1, mw * 32 + mf * 16, kb, lane, a1[mf]);
            }
#pragma unroll
            for (int nf2 = 0; nf2 < 2; nf2++) {
                unsigned b0[4], b1[4];
                ldsm4(B0, nw * 32 + nf2 * 16, kb, lane, b0);
                ldsm4(B1, nw * 32 + nf2 * 16, kb, lane, b1);
#pragma unroll
                for (int mf = 0; mf < 2; mf++)
#pragma unroll
                    for (int h = 0; h < 2; h++) {
                        float* C = acc[mf * 4 + nf2 * 2 + h];
                        MMA16816(C, a0[mf], b0[h], b0[h + 2]);   // h0*g0
                        MMA16816(C, a0[mf], b1[h], b1[h + 2]);   // h0*g1
                        MMA16816(C, a1[mf], b0[h], b0[h + 2]);   // h1*g0
                    }
            }
        }
    }
    __syncthreads();   // all mma done; stage smem reusable

    // ---------------- epilogue (4 threads per row) ----------------
    float* gsm = (float*)(sm_ + OFF_T);   // d2 staging [128][132]
    const int lr = lane >> 2, lc = (lane & 3) * 2;
#pragma unroll
    for (int mf = 0; mf < 2; mf++)
#pragma unroll
        for (int nf2 = 0; nf2 < 2; nf2++)
#pragma unroll
            for (int h = 0; h < 2; h++) {
                int row = mw * 32 + mf * 16 + lr;
                int col = nw * 32 + nf2 * 16 + h * 8 + lc;
                float* C = acc[mf * 4 + nf2 * 2 + h];
                gsm[row * 132 + col]           = C[0];
                gsm[row * 132 + col + 1]       = C[1];
                gsm[(row + 8) * 132 + col]     = C[2];
                gsm[(row + 8) * 132 + col + 1] = C[3];
            }
    __syncthreads();

    const int part = tid & 3;
    const int row = tid >> 2;
    float sum = 0.f, mv = -1.f;
    int mi = 0;
#pragma unroll 8
    for (int cc = 0; cc < 32; cc++) {
        int c = part * 32 + cc;
        float g = __expf(-0.5f * gsm[row * 132 + c]);
        sum += g;
        if (g > mv) { mv = g; mi = c; }
        atomicAdd(&lab_s[cls_s[c] * ROWS + row], g);
    }
#pragma unroll
    for (int m = 1; m <= 2; m <<= 1) {
        sum += __shfl_xor_sync(0xffffffffu, sum, m);
        float ov = __shfl_xor_sync(0xffffffffu, mv, m);
        int oi = __shfl_xor_sync(0xffffffffu, mi, m);
        if (ov > mv || (ov == mv && oi < mi)) { mv = ov; mi = oi; }
    }
    __syncthreads();   // label-bin atomics complete

    if (part == 0) {
        const size_t b = (size_t)blockIdx.x * ROWS + row;
        float inv = 1.f / (sum + 1e-12f);
        float best = -1.f;
        int kb = 0;
#pragma unroll
        for (int k = 0; k < Kn; k++) {
            float ls = lab_s[k * ROWS + row] * inv;
            out[b * Kn + k] = ls;
            if (ls > best) { best = ls; kb = k; }
        }
        out[(size_t)Bn * Kn + b] = (float)kb;
        out[(size_t)Bn * Kn + Bn + b] = (float)mi;
    }
}

extern "C" void kernel_launch(void* const* d_in, const int* in_sizes, int n_in,
                              void* d_out, int out_size) {
    const float* data = (const float*)d_in[0];   // [B, D]
    const float* mu   = (const float*)d_in[1];   // [C, D]
    const float* Sinv = (const float*)d_in[2];   // [C, D, D]
    const int*   lab  = (const int*)d_in[3];     // [C, K]
    float* out = (float*)d_out;

    static int smem_set = 0;
    if (!smem_set) {
        cudaFuncSetAttribute(gemm_kernel,
                             cudaFuncAttributeMaxDynamicSharedMemorySize, SMEM_SZ);
        smem_set = 1;
    }
    prep_kernel<<<Cn, 32>>>(mu, Sinv, lab);
    build_kernel<<<NBLK, 256>>>(data);
    gemm_kernel<<<NBLK, THREADS, SMEM_SZ>>>(out);
}

// round 9
// speedup vs baseline: 1.1865x; 1.1865x over previous
#include <cuda_runtime.h>
#include <cuda_fp16.h>

// ---------------- problem constants ----------------
#define Bn 65536
#define Cn 128
#define Dn 32
#define Kn 10
#define NAUG 33
#define KPAD 576          // padded triangular size (18 chunks of 32)
#define KC 32
#define NCH 18
#define ROWS 128
#define THREADS 256
#define TILE 8192         // 128 x 32 fp16, 64B rows, SW64

#define SWZ64(o) ((o) ^ (((o) >> 3) & 0x30))

// pre-split fp16 U tiles, pre-swizzled SW64: [split][chunk][8KB]
__device__ __align__(16) unsigned char g_Uh[2][NCH][TILE];
__device__ int g_ij[KPAD];     // (i | j<<8)
__device__ int g_cls[Cn];

// ---------------- helpers ----------------
static __device__ __forceinline__ unsigned smem_u32(const void* p) {
    unsigned a;
    asm("{ .reg .u64 t; cvta.to.shared.u64 t, %1; cvt.u32.u64 %0, t; }"
        : "=r"(a) : "l"(p));
    return a;
}
static __device__ __forceinline__ void cp16(unsigned sdst, const void* gsrc) {
    asm volatile("cp.async.cg.shared.global [%0], [%1], 16;" :: "r"(sdst), "l"(gsrc));
}
static __device__ __forceinline__ void ldsm4(unsigned base, int row0, int ks,
                                             int lane, unsigned* r) {
    unsigned off = (unsigned)((row0 + (lane & 15)) * 64 + ks * 32 + ((lane >> 4) << 4));
    unsigned addr = base + SWZ64(off);
    asm volatile("ldmatrix.sync.aligned.m8n8.x4.shared.b16 {%0,%1,%2,%3}, [%4];"
                 : "=r"(r[0]), "=r"(r[1]), "=r"(r[2]), "=r"(r[3]) : "r"(addr));
}
#define MMA16816(C, A, b0, b1) \
    asm volatile("mma.sync.aligned.m16n8k16.row.col.f32.f16.f16.f32 " \
        "{%0,%1,%2,%3}, {%4,%5,%6,%7}, {%8,%9}, {%0,%1,%2,%3};" \
        : "+f"((C)[0]), "+f"((C)[1]), "+f"((C)[2]), "+f"((C)[3]) \
        : "r"((A)[0]), "r"((A)[1]), "r"((A)[2]), "r"((A)[3]), "r"(b0), "r"(b1))

// triangular row start: s(i) = i*(2*NAUG+1-i)/2
static __device__ __forceinline__ int tri_start(int i) { return i * (67 - i) / 2; }

// ---------------- prep: split U into 2 fp16 SW64 tiles ----------------
__global__ void prep_kernel(const float* __restrict__ mu,
                            const float* __restrict__ S,
                            const int* __restrict__ lab) {
    const int c = blockIdx.x;
    const int t = threadIdx.x;   // 128
    __shared__ float mus[Dn], Sm[Dn], t3s;

    if (t < Dn) mus[t] = mu[c * Dn + t];
    __syncthreads();
    if (t < Dn) {
        float s = 0.f;
#pragma unroll
        for (int e = 0; e < Dn; e++) s += S[(c * Dn + t) * Dn + e] * mus[e];
        Sm[t] = s;
    }
    __syncthreads();
    if (t == 0) {
        float s = 0.f;
        for (int d = 0; d < Dn; d++) s += mus[d] * Sm[d];
        t3s = s;
        int cl = 0;
        for (int k = 0; k < Kn; k++) if (lab[c * Kn + k] != 0) cl = k;
        g_cls[c] = cl;
    }
    __syncthreads();

    for (int k = t; k < KPAD; k += 128) {
        float v; int ii, jj;
        if (k > 560) { v = 0.f; ii = 32; jj = 32; }
        else {
            int i = (int)((67.0f - sqrtf(4489.0f - 8.0f * (float)k)) * 0.5f);
            if (i > 32) i = 32;
            while (i > 0 && tri_start(i) > k) i--;
            while (tri_start(i + 1) <= k) i++;
            int j = i + (k - tri_start(i));
            ii = i; jj = j;
            if (j < Dn)      v = ((i == j) ? 1.f : 2.f) * S[(c * Dn + i) * Dn + j];
            else if (i < Dn) v = -2.f * Sm[i];
            else             v = t3s;
        }
        if (c == 0) g_ij[k] = ii | (jj << 8);

        __half h0 = __float2half_rn(v);
        float r = v - __half2float(h0);
        __half h1 = __float2half_rn(r);

        int ch = k >> 5, kk = k & 31;
        int sw = SWZ64(c * 64 + kk * 2);
        *(__half*)&g_Uh[0][ch][sw] = h0;
        *(__half*)&g_Uh[1][ch][sw] = h1;
    }
}

// ---------------- smem layout (bytes) ----------------
#define OFF_Z    0          // 33*129*4 = 17028 -> 17152
#define OFF_IJ   17152      // 2304 -> 19456
#define OFF_CLS  19456      // 512 -> 19968
#define OFF_LAB  19968      // 5120 -> 25088
#define OFF_SUM  25088      // 512 -> 25600
#define OFF_PMAX 25600      // 128*8 = 1024 -> 26624
#define OFF_T    26624      // A double 32K + B double 32K
#define SMEM_SZ  92160

// ---------------- main kernel: 2 blocks/SM target ----------------
__global__ void __launch_bounds__(THREADS, 2)
main_kernel(const float* __restrict__ data, float* __restrict__ out) {
    extern __shared__ char sm_[];
    int*    ij_s  = (int*)(sm_ + OFF_IJ);
    int*    cls_s = (int*)(sm_ + OFF_CLS);
    float*  lab_s = (float*)(sm_ + OFF_LAB);
    float*  sum_s = (float*)(sm_ + OFF_SUM);
    unsigned long long* pmax_s = (unsigned long long*)(sm_ + OFF_PMAX);
    float*  z_s   = (float*)(sm_ + OFF_Z);

    const int tid = threadIdx.x;
    const int wid = tid >> 5;
    const int lane = tid & 31;
    const int mw = wid >> 1;          // 0..3 -> rows mw*32
    const int nw = wid & 1;           // 0..1 -> cols nw*64
    const int bbase = blockIdx.x * ROWS;
    const unsigned sbase = smem_u32(sm_);

    const unsigned tAb = sbase + OFF_T;            // + buf*16384 + split*8192
    const unsigned tBb = tAb + 2 * 16384;          // + buf*16384 + split*8192

    // prologue
    if (tid < Cn) cls_s[tid] = g_cls[tid];
    for (int i = tid; i < Kn * ROWS; i += THREADS) lab_s[i] = 0.f;
    if (tid < ROWS) { sum_s[tid] = 0.f; pmax_s[tid] = 0ull; }
    for (int i = tid; i < KPAD; i += THREADS) ij_s[i] = g_ij[i];
    for (int idx = tid; idx < ROWS * Dn; idx += THREADS) {
        int row = idx >> 5, d = idx & 31;
        z_s[d * 129 + row] = data[(size_t)(bbase + row) * Dn + d];
    }
    if (tid < ROWS) z_s[32 * 129 + tid] = 1.f;

    // prefetch B chunk 0 into buf 0
#pragma unroll
    for (int s = 0; s < 2; s++)
        for (int e = tid; e < TILE / 16; e += THREADS)
            cp16(tBb + s * TILE + e * 16, &g_Uh[s][0][e * 16]);
    asm volatile("cp.async.commit_group;");
    __syncthreads();   // z_s / ij_s ready

    // build A chunk 0 into buf 0 (8 cells/thread; cell = kp*128 + row)
#pragma unroll
    for (int it = 0; it < 8; it++) {
        int cell = tid + it * THREADS;
        int kp = cell >> 7, row = cell & 127;
        int ij0 = ij_s[2 * kp], ij1 = ij_s[2 * kp + 1];
        float w0 = z_s[(ij0 & 255) * 129 + row] * z_s[(ij0 >> 8) * 129 + row];
        float w1 = z_s[(ij1 & 255) * 129 + row] * z_s[(ij1 >> 8) * 129 + row];
        __half h00 = __float2half_rn(w0), h01 = __float2half_rn(w1);
        float r0 = w0 - __half2float(h00);
        float r1 = w1 - __half2float(h01);
        __half2 p0 = __halves2half2(h00, h01);
        __half2 p1 = __halves2half2(__float2half_rn(r0), __float2half_rn(r1));
        unsigned sw = SWZ64((unsigned)(row * 64 + kp * 4));
        asm volatile("st.shared.b32 [%0], %1;" :: "r"(tAb + sw), "r"(*(unsigned*)&p0));
        asm volatile("st.shared.b32 [%0], %1;" :: "r"(tAb + TILE + sw), "r"(*(unsigned*)&p1));
    }

    float acc[16][4];
#pragma unroll
    for (int i = 0; i < 16; i++)
#pragma unroll
        for (int q = 0; q < 4; q++) acc[i][q] = 0.f;

    for (int ch = 0; ch < NCH; ch++) {
        const int cur = ch & 1;
        asm volatile("cp.async.wait_group 0;");   // B[cur] landed
        __syncthreads();                          // prev MMA + A[cur] build done

        if (ch + 1 < NCH) {                       // safe: all readers past barrier
            unsigned dst = tBb + (1 - cur) * 16384;
#pragma unroll
            for (int s = 0; s < 2; s++)
                for (int e = tid; e < TILE / 16; e += THREADS)
                    cp16(dst + s * TILE + e * 16, &g_Uh[s][ch + 1][e * 16]);
            asm volatile("cp.async.commit_group;");
        }

        const unsigned A0 = tAb + cur * 16384, A1 = A0 + TILE;
        const unsigned B0 = tBb + cur * 16384, B1 = B0 + TILE;
        const unsigned An0 = tAb + (1 - cur) * 16384, An1 = An0 + TILE;
        const int k0n = (ch + 1) * KC;

#pragma unroll
        for (int ks = 0; ks < 2; ks++) {
            unsigned a0[2][4], a1[2][4];
#pragma unroll
            for (int mf = 0; mf < 2; mf++) {
                ldsm4(A0, mw * 32 + mf * 16, ks, lane, a0[mf]);
                ldsm4(A1, mw * 32 + mf * 16, ks, lane, a1[mf]);
            }
#pragma unroll
            for (int nf2 = 0; nf2 < 4; nf2++) {
                unsigned b0[4], b1[4];
                ldsm4(B0, nw * 64 + nf2 * 16, ks, lane, b0);
                ldsm4(B1, nw * 64 + nf2 * 16, ks, lane, b1);
#pragma unroll
                for (int mf = 0; mf < 2; mf++)
#pragma unroll
                    for (int h = 0; h < 2; h++) {
                        float* C = acc[mf * 8 + nf2 * 2 + h];
                        MMA16816(C, a0[mf], b0[h], b0[h + 2]);   // h0*g0
                        MMA16816(C, a0[mf], b1[h], b1[h + 2]);   // h0*g1
                        MMA16816(C, a1[mf], b0[h], b0[h + 2]);   // h1*g0
                    }
            }
            // fused: build 4 cells of A[next]
            if (ch + 1 < NCH) {
#pragma unroll
                for (int t2 = 0; t2 < 4; t2++) {
                    int cell = tid + (ks * 4 + t2) * THREADS;
                    int kp = cell >> 7, row = cell & 127;
                    int ij0 = ij_s[k0n + 2 * kp], ij1 = ij_s[k0n + 2 * kp + 1];
                    float w0 = z_s[(ij0 & 255) * 129 + row] * z_s[(ij0 >> 8) * 129 + row];
                    float w1 = z_s[(ij1 & 255) * 129 + row] * z_s[(ij1 >> 8) * 129 + row];
                    __half h00 = __float2half_rn(w0), h01 = __float2half_rn(w1);
                    float r0 = w0 - __half2float(h00);
                    float r1 = w1 - __half2float(h01);
                    __half2 p0 = __halves2half2(h00, h01);
                    __half2 p1 = __halves2half2(__float2half_rn(r0), __float2half_rn(r1));
                    unsigned sw = SWZ64((unsigned)(row * 64 + kp * 4));
                    asm volatile("st.shared.b32 [%0], %1;" :: "r"(An0 + sw), "r"(*(unsigned*)&p0));
                    asm volatile("st.shared.b32 [%0], %1;" :: "r"(An1 + sw), "r"(*(unsigned*)&p1));
                }
            }
        }
    }
    __syncthreads();

    // ---------------- atomic epilogue (no d2 staging) ----------------
    const int lr = lane >> 2, lc = (lane & 3) * 2;
#pragma unroll
    for (int mf = 0; mf < 2; mf++) {
        float rsum[2] = {0.f, 0.f};
        unsigned long long rmax[2] = {0ull, 0ull};
#pragma unroll
        for (int nf2 = 0; nf2 < 4; nf2++)
#pragma unroll
            for (int h = 0; h < 2; h++) {
                float* C = acc[mf * 8 + nf2 * 2 + h];
                int col = nw * 64 + nf2 * 16 + h * 8 + lc;
                int row0 = mw * 32 + mf * 16 + lr;
#pragma unroll
                for (int q = 0; q < 4; q++) {
                    int rr = q >> 1;                 // 0: row0, 1: row0+8
                    int c = col + (q & 1);
                    float g = __expf(-0.5f * C[q]);
                    rsum[rr] += g;
                    unsigned long long pk =
                        ((unsigned long long)__float_as_uint(g) << 32) |
                        (unsigned)(127 - c);
                    if (pk > rmax[rr]) rmax[rr] = pk;
                    atomicAdd(&lab_s[cls_s[c] * ROWS + row0 + rr * 8], g);
                }
            }
#pragma unroll
        for (int rr = 0; rr < 2; rr++) {
            int row = mw * 32 + mf * 16 + lr + rr * 8;
            atomicAdd(&sum_s[row], rsum[rr]);
            atomicMax(&pmax_s[row], rmax[rr]);
        }
    }
    __syncthreads();

    if (tid < ROWS) {
        const int row = tid;
        const size_t b = (size_t)bbase + row;
        float inv = 1.f / (sum_s[row] + 1e-12f);
        float best = -1.f;
        int kb = 0;
#pragma unroll
        for (int k = 0; k < Kn; k++) {
            float ls = lab_s[k * ROWS + row] * inv;
            out[b * Kn + k] = ls;
            if (ls > best) { best = ls; kb = k; }
        }
        out[(size_t)Bn * Kn + b] = (float)kb;
        out[(size_t)Bn * Kn + Bn + b] = (float)(127 - (int)(pmax_s[row] & 0xFFu));
    }
}

extern "C" void kernel_launch(void* const* d_in, const int* in_sizes, int n_in,
                              void* d_out, int out_size) {
    const float* data = (const float*)d_in[0];   // [B, D]
    const float* mu   = (const float*)d_in[1];   // [C, D]
    const float* Sinv = (const float*)d_in[2];   // [C, D, D]
    const int*   lab  = (const int*)d_in[3];     // [C, K]
    float* out = (float*)d_out;

    static int smem_set = 0;
    if (!smem_set) {
        cudaFuncSetAttribute(main_kernel,
                             cudaFuncAttributeMaxDynamicSharedMemorySize, SMEM_SZ);
        smem_set = 1;
    }
    prep_kernel<<<Cn, 128>>>(mu, Sinv, lab);
    main_kernel<<<Bn / ROWS, THREADS, SMEM_SZ>>>(data, out);
}

// round 14
// speedup vs baseline: 1.2611x; 1.0629x over previous
#include <cuda_runtime.h>
#include <cuda_fp16.h>

// ---------------- problem constants ----------------
#define Bn 65536
#define Cn 128
#define Dn 32
#define Kn 10
#define NAUG 33
#define KPAD 576          // padded triangular size (18 chunks of 32)
#define KC 32
#define NCH 18
#define ROWS 128
#define THREADS 256
#define TILE 8192         // 128 x 32 fp16, 64B rows, SW64

#define SWZ64(o) ((o) ^ (((o) >> 3) & 0x30))

// pre-split fp16 U tiles, pre-swizzled SW64: [split][chunk][8KB]
__device__ __align__(16) unsigned char g_Uh[2][NCH][TILE];
__device__ unsigned g_ijoff[KPAD];   // (4*i) | (4*j << 16)  byte offsets into z row
__device__ int g_cls[Cn];

// ---------------- helpers ----------------
static __device__ __forceinline__ unsigned smem_u32(const void* p) {
    unsigned a;
    asm("{ .reg .u64 t; cvta.to.shared.u64 t, %1; cvt.u32.u64 %0, t; }"
        : "=r"(a) : "l"(p));
    return a;
}
static __device__ __forceinline__ void cp16(unsigned sdst, const void* gsrc) {
    asm volatile("cp.async.cg.shared.global [%0], [%1], 16;" :: "r"(sdst), "l"(gsrc));
}
static __device__ __forceinline__ void ldsm4(unsigned base, int row0, int ks,
                                             int lane, unsigned* r) {
    unsigned off = (unsigned)((row0 + (lane & 15)) * 64 + ks * 32 + ((lane >> 4) << 4));
    unsigned addr = base + SWZ64(off);
    asm volatile("ldmatrix.sync.aligned.m8n8.x4.shared.b16 {%0,%1,%2,%3}, [%4];"
                 : "=r"(r[0]), "=r"(r[1]), "=r"(r[2]), "=r"(r[3]) : "r"(addr));
}
#define MMA16816(C, A, b0, b1) \
    asm volatile("mma.sync.aligned.m16n8k16.row.col.f32.f16.f16.f32 " \
        "{%0,%1,%2,%3}, {%4,%5,%6,%7}, {%8,%9}, {%0,%1,%2,%3};" \
        : "+f"((C)[0]), "+f"((C)[1]), "+f"((C)[2]), "+f"((C)[3]) \
        : "r"((A)[0]), "r"((A)[1]), "r"((A)[2]), "r"((A)[3]), "r"(b0), "r"(b1))

static __device__ __forceinline__ float lds_f(unsigned a) {
    float v;
    asm("ld.shared.f32 %0, [%1];" : "=f"(v) : "r"(a));
    return v;
}
static __device__ __forceinline__ unsigned packh2(float hi, float lo) {
    unsigned p;
    asm("cvt.rn.f16x2.f32 %0, %1, %2;" : "=r"(p) : "f"(hi), "f"(lo));
    return p;
}

static __device__ __forceinline__ int tri_start(int i) { return i * (67 - i) / 2; }

// ---------------- prep: split U into 2 fp16 SW64 tiles + offset table ----------------
__global__ void prep_kernel(const float* __restrict__ mu,
                            const float* __restrict__ S,
                            const int* __restrict__ lab) {
    const int c = blockIdx.x;
    const int t = threadIdx.x;   // 128
    __shared__ float mus[Dn], Sm[Dn], t3s;

    if (t < Dn) mus[t] = mu[c * Dn + t];
    __syncthreads();
    if (t < Dn) {
        float s = 0.f;
#pragma unroll
        for (int e = 0; e < Dn; e++) s += S[(c * Dn + t) * Dn + e] * mus[e];
        Sm[t] = s;
    }
    __syncthreads();
    if (t == 0) {
        float s = 0.f;
        for (int d = 0; d < Dn; d++) s += mus[d] * Sm[d];
        t3s = s;
        int cl = 0;
        for (int k = 0; k < Kn; k++) if (lab[c * Kn + k] != 0) cl = k;
        g_cls[c] = cl;
    }
    __syncthreads();

    for (int k = t; k < KPAD; k += 128) {
        float v; int ii, jj;
        if (k > 560) { v = 0.f; ii = 33; jj = 33; }   // -> zero slot in z row
        else {
            int i = (int)((67.0f - sqrtf(4489.0f - 8.0f * (float)k)) * 0.5f);
            if (i > 32) i = 32;
            while (i > 0 && tri_start(i) > k) i--;
            while (tri_start(i + 1) <= k) i++;
            int j = i + (k - tri_start(i));
            ii = i; jj = j;
            if (j < Dn)      v = ((i == j) ? 1.f : 2.f) * S[(c * Dn + i) * Dn + j];
            else if (i < Dn) v = -2.f * Sm[i];
            else             v = t3s;
        }
        if (c == 0) g_ijoff[k] = (unsigned)(4 * ii) | ((unsigned)(4 * jj) << 16);

        __half h0 = __float2half_rn(v);
        float r = v - __half2float(h0);
        __half h1 = __float2half_rn(r);

        int ch = k >> 5, kk = k & 31;
        int sw = SWZ64(c * 64 + kk * 2);
        *(__half*)&g_Uh[0][ch][sw] = h0;
        *(__half*)&g_Uh[1][ch][sw] = h1;
    }
}

// ---------------- smem layout (bytes) ----------------
#define OFF_Z    0          // 128*37*4 = 18944
#define OFF_IJO  18944      // 2304 -> 21248
#define OFF_CLS  21248      // 512 -> 21760
#define OFF_LAB  21760      // 5120 -> 26880
#define OFF_SUM  26880      // 512 -> 27392
#define OFF_PMAX 27392      // 1024 -> 28416
#define OFF_T    28672      // A dbl 32768 + B triple 49152
#define SMEM_SZ  110592

// ---------------- main kernel: 2 blocks/SM ----------------
__global__ void __launch_bounds__(THREADS, 2)
main_kernel(const float* __restrict__ data, float* __restrict__ out) {
    extern __shared__ char sm_[];
    int*    cls_s = (int*)(sm_ + OFF_CLS);
    float*  lab_s = (float*)(sm_ + OFF_LAB);
    float*  sum_s = (float*)(sm_ + OFF_SUM);
    unsigned long long* pmax_s = (unsigned long long*)(sm_ + OFF_PMAX);
    float*  z_s   = (float*)(sm_ + OFF_Z);
    unsigned* ijo_s = (unsigned*)(sm_ + OFF_IJO);

    const int tid = threadIdx.x;
    const int wid = tid >> 5;
    const int lane = tid & 31;
    const int mw = wid >> 1;          // 0..3 -> rows mw*32
    const int nw = wid & 1;           // 0..1 -> cols nw*64
    const int bbase = blockIdx.x * ROWS;
    const unsigned sbase = smem_u32(sm_);

    const unsigned tAb = sbase + OFF_T;            // + buf*16384 + split*8192
    const unsigned tBb = tAb + 2 * 16384;          // + (ch%3)*16384 + split*8192

    // builder identity: one row, 8 kp half
    const int row_b = tid & 127;
    const int kp0_b = (tid >> 7) * 8;
    const unsigned zb = sbase + OFF_Z + (unsigned)row_b * 148;
    const unsigned rb64 = (unsigned)row_b * 64;
    const unsigned xorw = (rb64 >> 3) & 0x30;      // swizzle term (row-dependent)

    // prologue
    if (tid < Cn) cls_s[tid] = g_cls[tid];
    for (int i = tid; i < Kn * ROWS; i += THREADS) lab_s[i] = 0.f;
    if (tid < ROWS) { sum_s[tid] = 0.f; pmax_s[tid] = 0ull; }
    for (int i = tid; i < KPAD; i += THREADS) ijo_s[i] = g_ijoff[i];
    for (int idx = tid; idx < ROWS * Dn; idx += THREADS) {
        int row = idx >> 5, d = idx & 31;
        z_s[row * 37 + d] = data[(size_t)(bbase + row) * Dn + d];
    }
    if (tid < ROWS) { z_s[tid * 37 + 32] = 1.f; z_s[tid * 37 + 33] = 0.f; }

    // prefetch B chunks 0, 1 (separate commit groups)
#pragma unroll
    for (int st = 0; st < 2; st++) {
#pragma unroll
        for (int s = 0; s < 2; s++)
            for (int e = tid; e < TILE / 16; e += THREADS)
                cp16(tBb + st * 16384 + s * TILE + e * 16, &g_Uh[s][st][e * 16]);
        asm volatile("cp.async.commit_group;");
    }
    __syncthreads();   // z_s / ijo_s ready

    // build A chunk 0 into buf 0  (column offset swizzled BEFORE adding row base)
#pragma unroll
    for (int pp = 0; pp < 4; pp++) {
        int kp = kp0_b + pp * 2;
        uint2 o01 = *(const uint2*)(ijo_s + kp * 2);
        uint2 o23 = *(const uint2*)(ijo_s + kp * 2 + 2);
        float w0 = lds_f(zb + (o01.x & 0xFFFFu)) * lds_f(zb + (o01.x >> 16));
        float w1 = lds_f(zb + (o01.y & 0xFFFFu)) * lds_f(zb + (o01.y >> 16));
        float w2 = lds_f(zb + (o23.x & 0xFFFFu)) * lds_f(zb + (o23.x >> 16));
        float w3 = lds_f(zb + (o23.y & 0xFFFFu)) * lds_f(zb + (o23.y >> 16));
        unsigned ph01 = packh2(w1, w0), ph23 = packh2(w3, w2);
        float2 f01 = __half22float2(*(__half2*)&ph01);
        float2 f23 = __half22float2(*(__half2*)&ph23);
        unsigned pr01 = packh2(w1 - f01.y, w0 - f01.x);
        unsigned pr23 = packh2(w3 - f23.y, w2 - f23.x);
        unsigned aoff = rb64 + (((unsigned)(kp * 4)) ^ xorw);
        asm volatile("st.shared.v2.b32 [%0], {%1, %2};"
                     :: "r"(tAb + aoff), "r"(ph01), "r"(ph23));
        asm volatile("st.shared.v2.b32 [%0], {%1, %2};"
                     :: "r"(tAb + TILE + aoff), "r"(pr01), "r"(pr23));
    }

    float acc[16][4];
#pragma unroll
    for (int i = 0; i < 16; i++)
#pragma unroll
        for (int q = 0; q < 4; q++) acc[i][q] = 0.f;

    for (int ch = 0; ch < NCH; ch++) {
        const int cur = ch & 1;
        asm volatile("cp.async.wait_group 1;");   // B[ch] landed (B[ch+1] may fly)
        __syncthreads();                          // prev MMA + A[cur] build done

        if (ch + 2 < NCH) {
            unsigned dst = tBb + ((ch + 2) % 3) * 16384;
#pragma unroll
            for (int s = 0; s < 2; s++)
                for (int e = tid; e < TILE / 16; e += THREADS)
                    cp16(dst + s * TILE + e * 16, &g_Uh[s][ch + 2][e * 16]);
        }
        asm volatile("cp.async.commit_group;");   // uniform group counting

        const unsigned A0 = tAb + cur * 16384, A1 = A0 + TILE;
        const unsigned B0 = tBb + (ch % 3) * 16384, B1 = B0 + TILE;
        const unsigned An0 = tAb + (1 - cur) * 16384, An1 = An0 + TILE;
        const int k0n = (ch + 1) * KC;

#pragma unroll
        for (int ks = 0; ks < 2; ks++) {
            unsigned a0[2][4], a1[2][4];
#pragma unroll
            for (int mf = 0; mf < 2; mf++) {
                ldsm4(A0, mw * 32 + mf * 16, ks, lane, a0[mf]);
                ldsm4(A1, mw * 32 + mf * 16, ks, lane, a1[mf]);
            }
#pragma unroll
            for (int nf2 = 0; nf2 < 4; nf2++) {
                unsigned b0[4], b1[4];
                ldsm4(B0, nw * 64 + nf2 * 16, ks, lane, b0);
                ldsm4(B1, nw * 64 + nf2 * 16, ks, lane, b1);
#pragma unroll
                for (int mf = 0; mf < 2; mf++)
#pragma unroll
                    for (int h = 0; h < 2; h++) {
                        float* C = acc[mf * 8 + nf2 * 2 + h];
                        MMA16816(C, a0[mf], b0[h], b0[h + 2]);   // h0*g0
                        MMA16816(C, a0[mf], b1[h], b1[h + 2]);   // h0*g1
                        MMA16816(C, a1[mf], b0[h], b0[h + 2]);   // h1*g0
                    }
            }
            // fused: build 2 kp-pairs of A[next] (4 kp per ks iter)
            if (ch + 1 < NCH) {
#pragma unroll
                for (int pp = 0; pp < 2; pp++) {
                    int kp = kp0_b + ks * 4 + pp * 2;
                    uint2 o01 = *(const uint2*)(ijo_s + k0n + kp * 2);
                    uint2 o23 = *(const uint2*)(ijo_s + k0n + kp * 2 + 2);
                    float w0 = lds_f(zb + (o01.x & 0xFFFFu)) * lds_f(zb + (o01.x >> 16));
                    float w1 = lds_f(zb + (o01.y & 0xFFFFu)) * lds_f(zb + (o01.y >> 16));
                    float w2 = lds_f(zb + (o23.x & 0xFFFFu)) * lds_f(zb + (o23.x >> 16));
                    float w3 = lds_f(zb + (o23.y & 0xFFFFu)) * lds_f(zb + (o23.y >> 16));
                    unsigned ph01 = packh2(w1, w0), ph23 = packh2(w3, w2);
                    float2 f01 = __half22float2(*(__half2*)&ph01);
                    float2 f23 = __half22float2(*(__half2*)&ph23);
                    unsigned pr01 = packh2(w1 - f01.y, w0 - f01.x);
                    unsigned pr23 = packh2(w3 - f23.y, w2 - f23.x);
                    unsigned aoff = rb64 + (((unsigned)(kp * 4)) ^ xorw);
                    asm volatile("st.shared.v2.b32 [%0], {%1, %2};"
                                 :: "r"(An0 + aoff), "r"(ph01), "r"(ph23));
                    asm volatile("st.shared.v2.b32 [%0], {%1, %2};"
                                 :: "r"(An1 + aoff), "r"(pr01), "r"(pr23));
                }
            }
        }
    }
    __syncthreads();

    // ---------------- atomic epilogue ----------------
    const int lr = lane >> 2, lc = (lane & 3) * 2;
#pragma unroll
    for (int mf = 0; mf < 2; mf++) {
        float rsum[2] = {0.f, 0.f};
        unsigned long long rmax[2] = {0ull, 0ull};
#pragma unroll
        for (int nf2 = 0; nf2 < 4; nf2++)
#pragma unroll
            for (int h = 0; h < 2; h++) {
                float* C = acc[mf * 8 + nf2 * 2 + h];
                int col = nw * 64 + nf2 * 16 + h * 8 + lc;
                int row0 = mw * 32 + mf * 16 + lr;
#pragma unroll
                for (int q = 0; q < 4; q++) {
                    int rr = q >> 1;
                    int c = col + (q & 1);
                    float g = __expf(-0.5f * C[q]);
                    rsum[rr] += g;
                    unsigned long long pk =
                        ((unsigned long long)__float_as_uint(g) << 32) |
                        (unsigned)(127 - c);
                    if (pk > rmax[rr]) rmax[rr] = pk;
                    atomicAdd(&lab_s[cls_s[c] * ROWS + row0 + rr * 8], g);
                }
            }
#pragma unroll
        for (int rr = 0; rr < 2; rr++) {
            int row = mw * 32 + mf * 16 + lr + rr * 8;
            atomicAdd(&sum_s[row], rsum[rr]);
            atomicMax(&pmax_s[row], rmax[rr]);
        }
    }
    __syncthreads();

    if (tid < ROWS) {
        const int row = tid;
        const size_t b = (size_t)bbase + row;
        float inv = 1.f / (sum_s[row] + 1e-12f);
        float best = -1.f;
        int kb = 0;
#pragma unroll
        for (int k = 0; k < Kn; k++) {
            float ls = lab_s[k * ROWS + row] * inv;
            out[b * Kn + k] = ls;
            if (ls > best) { best = ls; kb = k; }
        }
        out[(size_t)Bn * Kn + b] = (float)kb;
        out[(size_t)Bn * Kn + Bn + b] = (float)(127 - (int)(pmax_s[row] & 0xFFu));
    }
}

extern "C" void kernel_launch(void* const* d_in, const int* in_sizes, int n_in,
                              void* d_out, int out_size) {
    const float* data = (const float*)d_in[0];   // [B, D]
    const float* mu   = (const float*)d_in[1];   // [C, D]
    const float* Sinv = (const float*)d_in[2];   // [C, D, D]
    const int*   lab  = (const int*)d_in[3];     // [C, K]
    float* out = (float*)d_out;

    static int smem_set = 0;
    if (!smem_set) {
        cudaFuncSetAttribute(main_kernel,
                             cudaFuncAttributeMaxDynamicSharedMemorySize, SMEM_SZ);
        smem_set = 1;
    }
    prep_kernel<<<Cn, 128>>>(mu, Sinv, lab);
    main_kernel<<<Bn / ROWS, THREADS, SMEM_SZ>>>(data, out);
}

// round 15
// speedup vs baseline: 1.3486x; 1.0694x over previous
#include <cuda_runtime.h>
#include <cuda_fp16.h>

// ---------------- problem constants ----------------
#define Bn 65536
#define Cn 128
#define Dn 32
#define Kn 10
#define NAUG 33
#define KPAD 576          // padded triangular size (18 chunks of 32)
#define KC 32
#define NCH 18
#define ROWS 128
#define THREADS 256
#define TILE 8192         // 128 x 32 fp16, 64B rows, SW64
#define GST 134           // gamma staging stride (floats)

#define SWZ64(o) ((o) ^ (((o) >> 3) & 0x30))

__device__ __align__(16) unsigned char g_Uh[2][NCH][TILE];
__device__ unsigned g_ijoff[KPAD];   // (4*i) | (4*j << 16) byte offsets into z row
__device__ int g_cls[Cn];

// ---------------- helpers ----------------
static __device__ __forceinline__ unsigned smem_u32(const void* p) {
    unsigned a;
    asm("{ .reg .u64 t; cvta.to.shared.u64 t, %1; cvt.u32.u64 %0, t; }"
        : "=r"(a) : "l"(p));
    return a;
}
static __device__ __forceinline__ void cp16(unsigned sdst, const void* gsrc) {
    asm volatile("cp.async.cg.shared.global [%0], [%1], 16;" :: "r"(sdst), "l"(gsrc));
}
static __device__ __forceinline__ void ldsm4a(unsigned addr, unsigned* r) {
    asm volatile("ldmatrix.sync.aligned.m8n8.x4.shared.b16 {%0,%1,%2,%3}, [%4];"
                 : "=r"(r[0]), "=r"(r[1]), "=r"(r[2]), "=r"(r[3]) : "r"(addr));
}
#define MMA16816(C, A, b0, b1) \
    asm volatile("mma.sync.aligned.m16n8k16.row.col.f32.f16.f16.f32 " \
        "{%0,%1,%2,%3}, {%4,%5,%6,%7}, {%8,%9}, {%0,%1,%2,%3};" \
        : "+f"((C)[0]), "+f"((C)[1]), "+f"((C)[2]), "+f"((C)[3]) \
        : "r"((A)[0]), "r"((A)[1]), "r"((A)[2]), "r"((A)[3]), "r"(b0), "r"(b1))

static __device__ __forceinline__ float lds_f(unsigned a) {
    float v;
    asm("ld.shared.f32 %0, [%1];" : "=f"(v) : "r"(a));
    return v;
}
static __device__ __forceinline__ unsigned packh2(float hi, float lo) {
    unsigned p;
    asm("cvt.rn.f16x2.f32 %0, %1, %2;" : "=r"(p) : "f"(hi), "f"(lo));
    return p;
}
static __device__ __forceinline__ int tri_start(int i) { return i * (67 - i) / 2; }

// ---------------- prep ----------------
__global__ void prep_kernel(const float* __restrict__ mu,
                            const float* __restrict__ S,
                            const int* __restrict__ lab) {
    const int c = blockIdx.x;
    const int t = threadIdx.x;   // 128
    __shared__ float mus[Dn], Sm[Dn], t3s;

    if (t < Dn) mus[t] = mu[c * Dn + t];
    __syncthreads();
    if (t < Dn) {
        float s = 0.f;
#pragma unroll
        for (int e = 0; e < Dn; e++) s += S[(c * Dn + t) * Dn + e] * mus[e];
        Sm[t] = s;
    }
    __syncthreads();
    if (t == 0) {
        float s = 0.f;
        for (int d = 0; d < Dn; d++) s += mus[d] * Sm[d];
        t3s = s;
        int cl = 0;
        for (int k = 0; k < Kn; k++) if (lab[c * Kn + k] != 0) cl = k;
        g_cls[c] = cl;
    }
    __syncthreads();

    for (int k = t; k < KPAD; k += 128) {
        float v; int ii, jj;
        if (k > 560) { v = 0.f; ii = 33; jj = 33; }
        else {
            int i = (int)((67.0f - sqrtf(4489.0f - 8.0f * (float)k)) * 0.5f);
            if (i > 32) i = 32;
            while (i > 0 && tri_start(i) > k) i--;
            while (tri_start(i + 1) <= k) i++;
            int j = i + (k - tri_start(i));
            ii = i; jj = j;
            if (j < Dn)      v = ((i == j) ? 1.f : 2.f) * S[(c * Dn + i) * Dn + j];
            else if (i < Dn) v = -2.f * Sm[i];
            else             v = t3s;
        }
        if (c == 0) g_ijoff[k] = (unsigned)(4 * ii) | ((unsigned)(4 * jj) << 16);

        __half h0 = __float2half_rn(v);
        float r = v - __half2float(h0);
        __half h1 = __float2half_rn(r);

        int ch = k >> 5, kk = k & 31;
        int sw = SWZ64(c * 64 + kk * 2);
        *(__half*)&g_Uh[0][ch][sw] = h0;
        *(__half*)&g_Uh[1][ch][sw] = h1;
    }
}

// ---------------- smem layout (bytes) ----------------
#define OFF_Z     0         // 128*37*4 = 18944
#define OFF_IJO   18944     // 2304 -> 21248
#define OFF_CLS   21248     // 512 -> 21760
#define OFF_LAB   21760     // 5120 -> 26880
#define OFF_CLIST 26880     // 512 -> 27392
#define OFF_PMAX  27392     // 1024 -> 28416
#define OFF_CNT   28416     // 40
#define OFF_COFF  28456     // 40 -> 28496
#define OFF_T     28672     // A dbl 32768 + B triple 49152; gamma staging reuse
#define SMEM_SZ   110592

// ---------------- main kernel: 2 blocks/SM ----------------
__global__ void __launch_bounds__(THREADS, 2)
main_kernel(const float* __restrict__ data, float* __restrict__ out) {
    extern __shared__ char sm_[];
    int*    cls_s  = (int*)(sm_ + OFF_CLS);
    float*  lab_s  = (float*)(sm_ + OFF_LAB);
    int*    clist_s= (int*)(sm_ + OFF_CLIST);
    unsigned long long* pmax_s = (unsigned long long*)(sm_ + OFF_PMAX);
    int*    cnt_s  = (int*)(sm_ + OFF_CNT);
    int*    coff_s = (int*)(sm_ + OFF_COFF);
    float*  z_s    = (float*)(sm_ + OFF_Z);
    unsigned* ijo_s= (unsigned*)(sm_ + OFF_IJO);
    float*  gsm    = (float*)(sm_ + OFF_T);   // [128][GST] post-MMA

    const int tid = threadIdx.x;
    const int wid = tid >> 5;
    const int lane = tid & 31;
    const int mw = wid >> 1;          // rows mw*32
    const int nw = wid & 1;           // cols nw*64
    const int bbase = blockIdx.x * ROWS;
    const unsigned sbase = smem_u32(sm_);

    const unsigned tAb = sbase + OFF_T;
    const unsigned tBb = tAb + 2 * 16384;

    // builder identity
    const int row_b = tid & 127;
    const int kp0_b = (tid >> 7) * 8;
    const unsigned zb = sbase + OFF_Z + (unsigned)row_b * 148;
    const unsigned rb64 = (unsigned)row_b * 64;
    const unsigned xorw = (rb64 >> 3) & 0x30;

    // hoisted swizzled LDSM fragment offsets
    unsigned offA[4], offB[8];
#pragma unroll
    for (int mf = 0; mf < 2; mf++)
#pragma unroll
        for (int ks = 0; ks < 2; ks++) {
            unsigned o = (unsigned)((mw * 32 + mf * 16 + (lane & 15)) * 64 +
                                    ks * 32 + ((lane >> 4) << 4));
            offA[mf * 2 + ks] = SWZ64(o);
        }
#pragma unroll
    for (int nf2 = 0; nf2 < 4; nf2++)
#pragma unroll
        for (int ks = 0; ks < 2; ks++) {
            unsigned o = (unsigned)((nw * 64 + nf2 * 16 + (lane & 15)) * 64 +
                                    ks * 32 + ((lane >> 4) << 4));
            offB[nf2 * 2 + ks] = SWZ64(o);
        }

    // prologue
    if (tid < Cn) cls_s[tid] = g_cls[tid];
    if (tid < ROWS) pmax_s[tid] = 0ull;
    if (tid < Kn) cnt_s[tid] = 0;
    for (int i = tid; i < KPAD; i += THREADS) ijo_s[i] = g_ijoff[i];
    for (int idx = tid; idx < ROWS * Dn; idx += THREADS) {
        int row = idx >> 5, d = idx & 31;
        z_s[row * 37 + d] = data[(size_t)(bbase + row) * Dn + d];
    }
    if (tid < ROWS) { z_s[tid * 37 + 32] = 1.f; z_s[tid * 37 + 33] = 0.f; }

    // prefetch B chunks 0, 1
#pragma unroll
    for (int st = 0; st < 2; st++) {
#pragma unroll
        for (int s = 0; s < 2; s++)
            for (int e = tid; e < TILE / 16; e += THREADS)
                cp16(tBb + st * 16384 + s * TILE + e * 16, &g_Uh[s][st][e * 16]);
        asm volatile("cp.async.commit_group;");
    }
    __syncthreads();   // z, cls, cnt-zero visible

    if (tid < Cn) atomicAdd(&cnt_s[cls_s[tid]], 1);

    // build A chunk 0 into buf 0
#pragma unroll
    for (int pp = 0; pp < 4; pp++) {
        int kp = kp0_b + pp * 2;
        uint2 o01 = *(const uint2*)(ijo_s + kp * 2);
        uint2 o23 = *(const uint2*)(ijo_s + kp * 2 + 2);
        float w0 = lds_f(zb + (o01.x & 0xFFFFu)) * lds_f(zb + (o01.x >> 16));
        float w1 = lds_f(zb + (o01.y & 0xFFFFu)) * lds_f(zb + (o01.y >> 16));
        float w2 = lds_f(zb + (o23.x & 0xFFFFu)) * lds_f(zb + (o23.x >> 16));
        float w3 = lds_f(zb + (o23.y & 0xFFFFu)) * lds_f(zb + (o23.y >> 16));
        unsigned ph01 = packh2(w1, w0), ph23 = packh2(w3, w2);
        float2 f01 = __half22float2(*(__half2*)&ph01);
        float2 f23 = __half22float2(*(__half2*)&ph23);
        unsigned pr01 = packh2(w1 - f01.y, w0 - f01.x);
        unsigned pr23 = packh2(w3 - f23.y, w2 - f23.x);
        unsigned aoff = rb64 + (((unsigned)(kp * 4)) ^ xorw);
        asm volatile("st.shared.v2.b32 [%0], {%1, %2};"
                     :: "r"(tAb + aoff), "r"(ph01), "r"(ph23));
        asm volatile("st.shared.v2.b32 [%0], {%1, %2};"
                     :: "r"(tAb + TILE + aoff), "r"(pr01), "r"(pr23));
    }

    float acc[16][4];
#pragma unroll
    for (int i = 0; i < 16; i++)
#pragma unroll
        for (int q = 0; q < 4; q++) acc[i][q] = 0.f;

    for (int ch = 0; ch < NCH; ch++) {
        const int cur = ch & 1;
        asm volatile("cp.async.wait_group 1;");
        __syncthreads();   // counts (ch0) / prev MMA + A[cur] build done

        // CSR build hidden under chunk-0 MMA (col_list used only in epilogue)
        if (ch == 0 && tid < Kn) {
            int off = 0;
            for (int j = 0; j < tid; j++) off += cnt_s[j];
            coff_s[tid] = off;
            for (int c = 0; c < Cn; c++)
                if (cls_s[c] == tid) clist_s[off++] = c;
        }

        if (ch + 2 < NCH) {
            unsigned dst = tBb + ((ch + 2) % 3) * 16384;
#pragma unroll
            for (int s = 0; s < 2; s++)
                for (int e = tid; e < TILE / 16; e += THREADS)
                    cp16(dst + s * TILE + e * 16, &g_Uh[s][ch + 2][e * 16]);
        }
        asm volatile("cp.async.commit_group;");

        const unsigned A0 = tAb + cur * 16384, A1 = A0 + TILE;
        const unsigned B0 = tBb + (ch % 3) * 16384, B1 = B0 + TILE;
        const unsigned An0 = tAb + (1 - cur) * 16384, An1 = An0 + TILE;
        const int k0n = (ch + 1) * KC;

#pragma unroll
        for (int ks = 0; ks < 2; ks++) {
            unsigned a0[2][4], a1[2][4];
#pragma unroll
            for (int mf = 0; mf < 2; mf++) {
                ldsm4a(A0 + offA[mf * 2 + ks], a0[mf]);
                ldsm4a(A1 + offA[mf * 2 + ks], a1[mf]);
            }
#pragma unroll
            for (int nf2 = 0; nf2 < 4; nf2++) {
                unsigned b0[4], b1[4];
                ldsm4a(B0 + offB[nf2 * 2 + ks], b0);
                ldsm4a(B1 + offB[nf2 * 2 + ks], b1);
#pragma unroll
                for (int mf = 0; mf < 2; mf++)
#pragma unroll
                    for (int h = 0; h < 2; h++) {
                        float* C = acc[mf * 8 + nf2 * 2 + h];
                        MMA16816(C, a0[mf], b0[h], b0[h + 2]);
                        MMA16816(C, a0[mf], b1[h], b1[h + 2]);
                        MMA16816(C, a1[mf], b0[h], b0[h + 2]);
                    }
            }
            if (ch + 1 < NCH) {
#pragma unroll
                for (int pp = 0; pp < 2; pp++) {
                    int kp = kp0_b + ks * 4 + pp * 2;
                    uint2 o01 = *(const uint2*)(ijo_s + k0n + kp * 2);
                    uint2 o23 = *(const uint2*)(ijo_s + k0n + kp * 2 + 2);
                    float w0 = lds_f(zb + (o01.x & 0xFFFFu)) * lds_f(zb + (o01.x >> 16));
                    float w1 = lds_f(zb + (o01.y & 0xFFFFu)) * lds_f(zb + (o01.y >> 16));
                    float w2 = lds_f(zb + (o23.x & 0xFFFFu)) * lds_f(zb + (o23.x >> 16));
                    float w3 = lds_f(zb + (o23.y & 0xFFFFu)) * lds_f(zb + (o23.y >> 16));
                    unsigned ph01 = packh2(w1, w0), ph23 = packh2(w3, w2);
                    float2 f01 = __half22float2(*(__half2*)&ph01);
                    float2 f23 = __half22float2(*(__half2*)&ph23);
                    unsigned pr01 = packh2(w1 - f01.y, w0 - f01.x);
                    unsigned pr23 = packh2(w3 - f23.y, w2 - f23.x);
                    unsigned aoff = rb64 + (((unsigned)(kp * 4)) ^ xorw);
                    asm volatile("st.shared.v2.b32 [%0], {%1, %2};"
                                 :: "r"(An0 + aoff), "r"(ph01), "r"(ph23));
                    asm volatile("st.shared.v2.b32 [%0], {%1, %2};"
                                 :: "r"(An1 + aoff), "r"(pr01), "r"(pr23));
                }
            }
        }
    }
    __syncthreads();   // MMA done; tile smem -> gamma staging

    // ---------------- phase 1: exp + stage gamma + argmax ----------------
    const int lr = lane >> 2, lc = (lane & 3) * 2;
#pragma unroll
    for (int mf = 0; mf < 2; mf++) {
        unsigned long long rmax[2] = {0ull, 0ull};
        const int row0 = mw * 32 + mf * 16 + lr;
#pragma unroll
        for (int nf2 = 0; nf2 < 4; nf2++)
#pragma unroll
            for (int h = 0; h < 2; h++) {
                float* C = acc[mf * 8 + nf2 * 2 + h];
                int col = nw * 64 + nf2 * 16 + h * 8 + lc;
                float g0 = __expf(-0.5f * C[0]);
                float g1 = __expf(-0.5f * C[1]);
                float g2 = __expf(-0.5f * C[2]);
                float g3 = __expf(-0.5f * C[3]);
                *(float2*)&gsm[row0 * GST + col]       = make_float2(g0, g1);
                *(float2*)&gsm[(row0 + 8) * GST + col] = make_float2(g2, g3);
                unsigned long long p0 =
                    ((unsigned long long)__float_as_uint(g0) << 32) | (unsigned)(127 - col);
                unsigned long long p1 =
                    ((unsigned long long)__float_as_uint(g1) << 32) | (unsigned)(126 - col);
                unsigned long long p2 =
                    ((unsigned long long)__float_as_uint(g2) << 32) | (unsigned)(127 - col);
                unsigned long long p3 =
                    ((unsigned long long)__float_as_uint(g3) << 32) | (unsigned)(126 - col);
                if (p0 > rmax[0]) rmax[0] = p0;
                if (p1 > rmax[0]) rmax[0] = p1;
                if (p2 > rmax[1]) rmax[1] = p2;
                if (p3 > rmax[1]) rmax[1] = p3;
            }
        // merge the 4 lanes sharing each row
#pragma unroll
        for (int m = 1; m <= 2; m <<= 1) {
#pragma unroll
            for (int rr = 0; rr < 2; rr++) {
                unsigned long long o = __shfl_xor_sync(0xffffffffu, rmax[rr], m);
                if (o > rmax[rr]) rmax[rr] = o;
            }
        }
        if ((lane & 3) == 0) {
            atomicMax(&pmax_s[row0], rmax[0]);
            atomicMax(&pmax_s[row0 + 8], rmax[1]);
        }
    }
    __syncthreads();

    // ---------------- phase 2: class-binned sums (no atomics) ----------------
#pragma unroll
    for (int it = 0; it < 5; it++) {
        int u = it * THREADS + tid;        // 1280 units: k = u>>7, row = u&127
        int k = u >> 7, row = u & 127;
        int off = coff_s[k], n = cnt_s[k];
        float s = 0.f;
        for (int p = 0; p < n; p++) s += gsm[row * GST + clist_s[off + p]];
        lab_s[k * ROWS + row] = s;
    }
    __syncthreads();

    // ---------------- final: normalize + outputs ----------------
    if (tid < ROWS) {
        const int row = tid;
        const size_t b = (size_t)bbase + row;
        float bins[Kn];
        float S = 0.f;
#pragma unroll
        for (int k = 0; k < Kn; k++) { bins[k] = lab_s[k * ROWS + row]; S += bins[k]; }
        float inv = 1.f / (S + 1e-12f);
        float best = -1.f;
        int kb = 0;
#pragma unroll
        for (int k = 0; k < Kn; k++) {
            float ls = bins[k] * inv;
            out[b * Kn + k] = ls;
            if (ls > best) { best = ls; kb = k; }
        }
        out[(size_t)Bn * Kn + b] = (float)kb;
        out[(size_t)Bn * Kn + Bn + b] = (float)(127 - (int)(pmax_s[row] & 0xFFu));
    }
}

extern "C" void kernel_launch(void* const* d_in, const int* in_sizes, int n_in,
                              void* d_out, int out_size) {
    const float* data = (const float*)d_in[0];
    const float* mu   = (const float*)d_in[1];
    const float* Sinv = (const float*)d_in[2];
    const int*   lab  = (const int*)d_in[3];
    float* out = (float*)d_out;

    static int smem_set = 0;
    if (!smem_set) {
        cudaFuncSetAttribute(main_kernel,
                             cudaFuncAttributeMaxDynamicSharedMemorySize, SMEM_SZ);
        smem_set = 1;
    }
    prep_kernel<<<Cn, 128>>>(mu, Sinv, lab);
    main_kernel<<<Bn / ROWS, THREADS, SMEM_SZ>>>(data, out);
}